// round 1
// baseline (speedup 1.0000x reference)
#include <cuda_runtime.h>
#include <math.h>

#define D_MODEL 1024
#define SEQ     4096
#define BATCH   4
#define NTOK    (BATCH * SEQ)     // 16384
#define NHEADS  16
#define DK      64
#define EPS     1e-6f

// ---------------- scratch (static device globals; no allocation) ----------------
__device__ float g_Q[(size_t)NTOK * D_MODEL];
__device__ float g_K[(size_t)NTOK * D_MODEL];
__device__ float g_V[(size_t)NTOK * D_MODEL];
__device__ float g_A[(size_t)NTOK * D_MODEL];
__device__ float g_kv[BATCH * NHEADS * DK * DK];
__device__ float g_ksum[BATCH * NHEADS * DK];

// ---------------- GEMM: C[M,N] = A[M,K] @ B[K,N] + bias, optional elu+1 ----------
// 128x128 block tile, K-tile 8, 256 threads, 8x8 per-thread micro-tile.
// FMAP=1 applies f(v) = v>0 ? v+1 : exp(v)  (== elu(v)+1)
template <int FMAP>
__global__ __launch_bounds__(256) void gemm128(const float* __restrict__ A,
                                               const float* __restrict__ B,
                                               const float* __restrict__ bias,
                                               float* __restrict__ C,
                                               int M, int N, int K) {
    __shared__ float As[8][128];
    __shared__ float Bs[8][128];

    const int tid = threadIdx.x;
    const int m0 = blockIdx.y * 128;
    const int n0 = blockIdx.x * 128;

    const int aRow = tid >> 1;          // 0..127
    const int aK4  = (tid & 1) * 4;     // 0 or 4
    const int bRow = tid >> 5;          // 0..7
    const int bCol = (tid & 31) * 4;    // 0..124

    const int tx = tid & 15;
    const int ty = tid >> 4;
    const int mf = ty * 8;
    const int nf = tx * 8;

    float acc[8][8];
#pragma unroll
    for (int i = 0; i < 8; i++)
#pragma unroll
        for (int j = 0; j < 8; j++) acc[i][j] = 0.0f;

    const float* Aptr = A + (size_t)(m0 + aRow) * K + aK4;
    const float* Bptr = B + (size_t)bRow * N + n0 + bCol;

    for (int kt = 0; kt < K; kt += 8) {
        float4 av = *(const float4*)(Aptr + kt);
        As[aK4 + 0][aRow] = av.x;
        As[aK4 + 1][aRow] = av.y;
        As[aK4 + 2][aRow] = av.z;
        As[aK4 + 3][aRow] = av.w;
        float4 bv = *(const float4*)(Bptr + (size_t)kt * N);
        *(float4*)&Bs[bRow][bCol] = bv;
        __syncthreads();

#pragma unroll
        for (int k = 0; k < 8; k++) {
            float a[8], b[8];
            *(float4*)(a)     = *(float4*)&As[k][mf];
            *(float4*)(a + 4) = *(float4*)&As[k][mf + 4];
            *(float4*)(b)     = *(float4*)&Bs[k][nf];
            *(float4*)(b + 4) = *(float4*)&Bs[k][nf + 4];
#pragma unroll
            for (int i = 0; i < 8; i++)
#pragma unroll
                for (int j = 0; j < 8; j++) acc[i][j] = fmaf(a[i], b[j], acc[i][j]);
        }
        __syncthreads();
    }

    // epilogue: bias (+ optional feature map), vectorized stores
#pragma unroll
    for (int i = 0; i < 8; i++) {
        const size_t mrow = (size_t)(m0 + mf + i) * N;
#pragma unroll
        for (int jj = 0; jj < 8; jj += 4) {
            float4 bb = *(const float4*)(bias + n0 + nf + jj);
            float4 o;
            float v0 = acc[i][jj + 0] + bb.x;
            float v1 = acc[i][jj + 1] + bb.y;
            float v2 = acc[i][jj + 2] + bb.z;
            float v3 = acc[i][jj + 3] + bb.w;
            if (FMAP) {
                v0 = (v0 > 0.0f) ? v0 + 1.0f : expf(v0);
                v1 = (v1 > 0.0f) ? v1 + 1.0f : expf(v1);
                v2 = (v2 > 0.0f) ? v2 + 1.0f : expf(v2);
                v3 = (v3 > 0.0f) ? v3 + 1.0f : expf(v3);
            }
            o.x = v0; o.y = v1; o.z = v2; o.w = v3;
            *(float4*)(C + mrow + n0 + nf + jj) = o;
        }
    }
}

// ---------------- kv accumulation: kv[bh] = K_h^T @ V_h ; ksum[bh] = sum_s k -----
__global__ __launch_bounds__(256) void kv_kernel(const float* __restrict__ Kb,
                                                 const float* __restrict__ Vb,
                                                 float* __restrict__ kvout,
                                                 float* __restrict__ ksumout) {
    const int bh = blockIdx.x;
    const int b = bh >> 4;
    const int h = bh & 15;

    __shared__ float Ks[32][64];
    __shared__ float Vs[32][64];

    const int tid = threadIdx.x;
    const int tx = tid & 15;
    const int ty = tid >> 4;
    const int d0 = ty * 4;
    const int e0 = tx * 4;

    float acc[4][4];
#pragma unroll
    for (int i = 0; i < 4; i++)
#pragma unroll
        for (int j = 0; j < 4; j++) acc[i][j] = 0.0f;
    float ks[4] = {0.f, 0.f, 0.f, 0.f};

    const float* Kbase = Kb + (size_t)b * SEQ * D_MODEL + h * 64;
    const float* Vbase = Vb + (size_t)b * SEQ * D_MODEL + h * 64;

    for (int s0 = 0; s0 < SEQ; s0 += 32) {
        for (int i = tid; i < 512; i += 256) {  // 512 float4s = 32 rows x 64 cols
            int r = i >> 4;
            int c4 = (i & 15) * 4;
            *(float4*)&Ks[r][c4] = *(const float4*)(Kbase + (size_t)(s0 + r) * D_MODEL + c4);
            *(float4*)&Vs[r][c4] = *(const float4*)(Vbase + (size_t)(s0 + r) * D_MODEL + c4);
        }
        __syncthreads();

#pragma unroll 8
        for (int s = 0; s < 32; s++) {
            float kd[4], ve[4];
            *(float4*)kd = *(float4*)&Ks[s][d0];
            *(float4*)ve = *(float4*)&Vs[s][e0];
#pragma unroll
            for (int i = 0; i < 4; i++) {
#pragma unroll
                for (int j = 0; j < 4; j++) acc[i][j] = fmaf(kd[i], ve[j], acc[i][j]);
            }
            if (tx == 0) {
#pragma unroll
                for (int i = 0; i < 4; i++) ks[i] += kd[i];
            }
        }
        __syncthreads();
    }

#pragma unroll
    for (int i = 0; i < 4; i++) {
        float4 o;
        o.x = acc[i][0]; o.y = acc[i][1]; o.z = acc[i][2]; o.w = acc[i][3];
        *(float4*)(kvout + (size_t)bh * 4096 + (d0 + i) * 64 + e0) = o;
    }
    if (tx == 0) {
#pragma unroll
        for (int i = 0; i < 4; i++) ksumout[bh * 64 + d0 + i] = ks[i];
    }
}

// ---------------- attention core: out = (q @ kv) / (q . ksum + eps) --------------
__global__ __launch_bounds__(256) void attn_kernel(const float* __restrict__ Qb,
                                                   const float* __restrict__ kv,
                                                   const float* __restrict__ ksum,
                                                   float* __restrict__ Ab) {
    const int bh = blockIdx.x;
    const int b = bh >> 4;
    const int h = bh & 15;
    const int s0 = blockIdx.y * 64;

    __shared__ float kvs[64][64];
    __shared__ float qs[64][64];
    __shared__ float kss[64];

    const int tid = threadIdx.x;

    // load kv tile (4096 floats)
    {
        const float4* src = (const float4*)(kv + (size_t)bh * 4096);
        float4* dst = (float4*)&kvs[0][0];
        for (int i = tid; i < 1024; i += 256) dst[i] = src[i];
    }
    // load q tile (64 rows x 64 cols)
    for (int i = tid; i < 64 * 16; i += 256) {
        int r = i >> 4;
        int c4 = (i & 15) * 4;
        *(float4*)&qs[r][c4] =
            *(const float4*)(Qb + (size_t)(b * SEQ + s0 + r) * D_MODEL + h * 64 + c4);
    }
    if (tid < 16) ((float4*)kss)[tid] = ((const float4*)(ksum + bh * 64))[tid];
    __syncthreads();

    const int e = tid & 63;
    const int tsub = tid >> 6;
    for (int t = tsub; t < 64; t += 4) {
        float z = 0.0f, o = 0.0f;
#pragma unroll 16
        for (int d = 0; d < 64; d++) {
            float qd = qs[t][d];
            z = fmaf(qd, kss[d], z);
            o = fmaf(qd, kvs[d][e], o);
        }
        Ab[(size_t)(b * SEQ + s0 + t) * D_MODEL + h * 64 + e] = o / (z + EPS);
    }
}

// ---------------- launch ---------------------------------------------------------
extern "C" void kernel_launch(void* const* d_in, const int* in_sizes, int n_in,
                              void* d_out, int out_size) {
    const float* x  = (const float*)d_in[0];
    const float* Wq = (const float*)d_in[1];
    const float* bq = (const float*)d_in[2];
    const float* Wk = (const float*)d_in[3];
    const float* bk = (const float*)d_in[4];
    const float* Wv = (const float*)d_in[5];
    const float* bv = (const float*)d_in[6];
    const float* Wo = (const float*)d_in[7];
    const float* bo = (const float*)d_in[8];
    float* out = (float*)d_out;

    float *Q, *K, *V, *A, *kv, *ksum;
    cudaGetSymbolAddress((void**)&Q, g_Q);
    cudaGetSymbolAddress((void**)&K, g_K);
    cudaGetSymbolAddress((void**)&V, g_V);
    cudaGetSymbolAddress((void**)&A, g_A);
    cudaGetSymbolAddress((void**)&kv, g_kv);
    cudaGetSymbolAddress((void**)&ksum, g_ksum);

    dim3 grid(D_MODEL / 128, NTOK / 128);  // (8, 128)
    gemm128<1><<<grid, 256>>>(x, Wq, bq, Q, NTOK, D_MODEL, D_MODEL);
    gemm128<1><<<grid, 256>>>(x, Wk, bk, K, NTOK, D_MODEL, D_MODEL);
    gemm128<0><<<grid, 256>>>(x, Wv, bv, V, NTOK, D_MODEL, D_MODEL);

    kv_kernel<<<BATCH * NHEADS, 256>>>(K, V, kv, ksum);
    attn_kernel<<<dim3(BATCH * NHEADS, SEQ / 64), 256>>>(Q, kv, ksum, A);

    gemm128<0><<<grid, 256>>>(A, Wo, bo, out, NTOK, D_MODEL, D_MODEL);
}

// round 2
// speedup vs baseline: 3.1284x; 3.1284x over previous
#include <cuda_runtime.h>
#include <math.h>
#include <stdint.h>

#define D_MODEL 1024
#define SEQ     4096
#define BATCH   4
#define NTOK    16384
#define NHEADS  16
#define EPS     1e-6f
#define KCH     8          // kv seq chunks

// ---------------- scratch ----------------
__device__ float g_Q[(size_t)NTOK * D_MODEL];
__device__ float g_K[(size_t)NTOK * D_MODEL];
__device__ float g_V[(size_t)NTOK * D_MODEL];
__device__ float g_A[(size_t)NTOK * D_MODEL];
__device__ float g_Xr[(size_t)NTOK * D_MODEL];
__device__ float g_Wr[4][(size_t)D_MODEL * D_MODEL];
__device__ float g_kvp[KCH * 64 * 4096];
__device__ float g_ksp[KCH * 64 * 64];
__device__ float g_kv[64 * 4096];
__device__ float g_ks[64 * 64];

// ---------------- tf32 rounding (RNA) ----------------
__global__ void round_tf32_kernel(const float4* __restrict__ in,
                                  float4* __restrict__ out, int n4) {
    int i = blockIdx.x * blockDim.x + threadIdx.x;
    if (i >= n4) return;
    float4 v = in[i];
    unsigned a, b, c, d;
    asm("cvt.rna.tf32.f32 %0, %1;" : "=r"(a) : "f"(v.x));
    asm("cvt.rna.tf32.f32 %0, %1;" : "=r"(b) : "f"(v.y));
    asm("cvt.rna.tf32.f32 %0, %1;" : "=r"(c) : "f"(v.z));
    asm("cvt.rna.tf32.f32 %0, %1;" : "=r"(d) : "f"(v.w));
    out[i] = make_float4(__uint_as_float(a), __uint_as_float(b),
                         __uint_as_float(c), __uint_as_float(d));
}

// ---------------- tf32 tensor-core GEMM ----------------
// C[M,1024] = A[M,1024] @ B[1024,1024] + bias, optional elu+1.
// Block 128x128, Ktile 32, 256 thr (8 warps, 2x4 warp grid, warp tile 64x32).
// A in smem row-major stride 36 (ldmatrix-friendly, conflict-free);
// B in smem [k][n] stride 136 (conflict-free scalar frag loads).
#define ASZ (128 * 36)
#define BSZ (32 * 136)
#define GEMM_SMEM (2 * (ASZ + BSZ) * 4)

__device__ __forceinline__ void cpasync16(uint32_t dst, const float* src) {
    asm volatile("cp.async.cg.shared.global [%0], [%1], 16;\n" ::"r"(dst), "l"(src));
}

__device__ __forceinline__ void load_tile(const float* __restrict__ Ag,
                                          const float* __restrict__ Bg,
                                          float* bufA, float* bufB,
                                          int m0, int n0, int kt, int tid) {
    const float* Asrc = Ag + (size_t)m0 * 1024 + kt * 32;
    const float* Bsrc = Bg + (size_t)kt * 32 * 1024 + n0;
#pragma unroll
    for (int j = 0; j < 4; j++) {
        int idx = tid + j * 256;
        int ar = idx >> 3, ac = (idx & 7) * 4;
        cpasync16((uint32_t)__cvta_generic_to_shared(bufA + ar * 36 + ac),
                  Asrc + (size_t)ar * 1024 + ac);
        int br = idx >> 5, bc = (idx & 31) * 4;
        cpasync16((uint32_t)__cvta_generic_to_shared(bufB + br * 136 + bc),
                  Bsrc + (size_t)br * 1024 + bc);
    }
    asm volatile("cp.async.commit_group;\n" ::: "memory");
}

template <int FMAP>
__global__ void __launch_bounds__(256) gemm_tf32(const float* __restrict__ Ag,
                                                 const float* __restrict__ Bg,
                                                 const float* __restrict__ bias,
                                                 float* __restrict__ C) {
    extern __shared__ float sm[];
    float* bufA[2] = {sm, sm + ASZ + BSZ};
    float* bufB[2] = {sm + ASZ, sm + 2 * ASZ + BSZ};

    const int tid = threadIdx.x;
    const int lane = tid & 31;
    const int w = tid >> 5;
    const int wm = w & 1;       // 0..1 -> m offset *64
    const int wn = w >> 1;      // 0..3 -> n offset *32
    const int m0 = blockIdx.y * 128, n0 = blockIdx.x * 128;

    // ldmatrix address pattern for A fragments
    const int lrow = lane & 7, lsel = lane >> 3;
    const int a_row = wm * 64 + ((lsel & 1) << 3) + lrow;
    const int a_col = (lsel >> 1) << 2;
    uint32_t aBase[2];
    aBase[0] = (uint32_t)__cvta_generic_to_shared(bufA[0] + a_row * 36 + a_col);
    aBase[1] = (uint32_t)__cvta_generic_to_shared(bufA[1] + a_row * 36 + a_col);
    const float* bBase[2] = {bufB[0] + (lane & 3) * 136 + wn * 32 + (lane >> 2),
                             bufB[1] + (lane & 3) * 136 + wn * 32 + (lane >> 2)};

    float acc[4][4][4];
#pragma unroll
    for (int i = 0; i < 4; i++)
#pragma unroll
        for (int j = 0; j < 4; j++)
#pragma unroll
            for (int r = 0; r < 4; r++) acc[i][j][r] = 0.0f;

    load_tile(Ag, Bg, bufA[0], bufB[0], m0, n0, 0, tid);

    for (int kt = 0; kt < 32; kt++) {
        asm volatile("cp.async.wait_group 0;\n" ::: "memory");
        __syncthreads();
        if (kt < 31)
            load_tile(Ag, Bg, bufA[(kt + 1) & 1], bufB[(kt + 1) & 1], m0, n0, kt + 1, tid);
        const int cb = kt & 1;
#pragma unroll
        for (int kk = 0; kk < 4; kk++) {
            uint32_t a[4][4];
#pragma unroll
            for (int mf = 0; mf < 4; mf++) {
                uint32_t addr = aBase[cb] + (uint32_t)((mf * 16 * 36 + kk * 8) * 4);
                asm volatile(
                    "ldmatrix.sync.aligned.m8n8.x4.shared.b16 {%0,%1,%2,%3}, [%4];"
                    : "=r"(a[mf][0]), "=r"(a[mf][1]), "=r"(a[mf][2]), "=r"(a[mf][3])
                    : "r"(addr));
            }
            uint32_t bf[4][2];
            const float* bb = bBase[cb] + kk * 8 * 136;
#pragma unroll
            for (int nf = 0; nf < 4; nf++) {
                bf[nf][0] = __float_as_uint(bb[nf * 8]);
                bf[nf][1] = __float_as_uint(bb[nf * 8 + 4 * 136]);
            }
#pragma unroll
            for (int mf = 0; mf < 4; mf++)
#pragma unroll
                for (int nf = 0; nf < 4; nf++)
                    asm volatile(
                        "mma.sync.aligned.m16n8k8.row.col.f32.tf32.tf32.f32 "
                        "{%0,%1,%2,%3}, {%4,%5,%6,%7}, {%8,%9}, {%0,%1,%2,%3};"
                        : "+f"(acc[mf][nf][0]), "+f"(acc[mf][nf][1]),
                          "+f"(acc[mf][nf][2]), "+f"(acc[mf][nf][3])
                        : "r"(a[mf][0]), "r"(a[mf][1]), "r"(a[mf][2]), "r"(a[mf][3]),
                          "r"(bf[nf][0]), "r"(bf[nf][1]));
        }
    }

    // epilogue
    const int gr = lane >> 2, gc2 = (lane & 3) * 2;
#pragma unroll
    for (int mf = 0; mf < 4; mf++) {
        int r0 = m0 + wm * 64 + mf * 16 + gr;
#pragma unroll
        for (int nf = 0; nf < 4; nf++) {
            int col = n0 + wn * 32 + nf * 8 + gc2;
            float2 bb = *(const float2*)(bias + col);
            float v0 = acc[mf][nf][0] + bb.x;
            float v1 = acc[mf][nf][1] + bb.y;
            float v2 = acc[mf][nf][2] + bb.x;
            float v3 = acc[mf][nf][3] + bb.y;
            if (FMAP) {
                v0 = (v0 > 0.0f) ? v0 + 1.0f : expf(v0);
                v1 = (v1 > 0.0f) ? v1 + 1.0f : expf(v1);
                v2 = (v2 > 0.0f) ? v2 + 1.0f : expf(v2);
                v3 = (v3 > 0.0f) ? v3 + 1.0f : expf(v3);
            }
            float2 o0 = {v0, v1}, o1 = {v2, v3};
            *(float2*)(C + (size_t)r0 * 1024 + col) = o0;
            *(float2*)(C + (size_t)(r0 + 8) * 1024 + col) = o1;
        }
    }
}

// ---------------- kv partial: per (bh, chunk) K^T@V over 512 seq rows ----------
__global__ __launch_bounds__(256) void kv_kernel(const float* __restrict__ Kb,
                                                 const float* __restrict__ Vb,
                                                 float* __restrict__ kvp,
                                                 float* __restrict__ ksp) {
    const int bh = blockIdx.x;
    const int ch = blockIdx.y;
    const int b = bh >> 4;
    const int h = bh & 15;

    __shared__ float Ks[32][64];
    __shared__ float Vs[32][64];

    const int tid = threadIdx.x;
    const int tx = tid & 15;
    const int ty = tid >> 4;
    const int d0 = ty * 4;
    const int e0 = tx * 4;

    float acc[4][4];
#pragma unroll
    for (int i = 0; i < 4; i++)
#pragma unroll
        for (int j = 0; j < 4; j++) acc[i][j] = 0.0f;
    float ks[4] = {0.f, 0.f, 0.f, 0.f};

    const float* Kbase = Kb + (size_t)b * SEQ * D_MODEL + h * 64;
    const float* Vbase = Vb + (size_t)b * SEQ * D_MODEL + h * 64;
    const int sBeg = ch * (SEQ / KCH);

    for (int s0 = sBeg; s0 < sBeg + SEQ / KCH; s0 += 32) {
        for (int i = tid; i < 512; i += 256) {
            int r = i >> 4;
            int c4 = (i & 15) * 4;
            *(float4*)&Ks[r][c4] = *(const float4*)(Kbase + (size_t)(s0 + r) * D_MODEL + c4);
            *(float4*)&Vs[r][c4] = *(const float4*)(Vbase + (size_t)(s0 + r) * D_MODEL + c4);
        }
        __syncthreads();

#pragma unroll 8
        for (int s = 0; s < 32; s++) {
            float kd[4], ve[4];
            *(float4*)kd = *(float4*)&Ks[s][d0];
            *(float4*)ve = *(float4*)&Vs[s][e0];
#pragma unroll
            for (int i = 0; i < 4; i++)
#pragma unroll
                for (int j = 0; j < 4; j++) acc[i][j] = fmaf(kd[i], ve[j], acc[i][j]);
            if (tx == 0) {
#pragma unroll
                for (int i = 0; i < 4; i++) ks[i] += kd[i];
            }
        }
        __syncthreads();
    }

    float* kvo = kvp + ((size_t)ch * 64 + bh) * 4096;
#pragma unroll
    for (int i = 0; i < 4; i++) {
        float4 o;
        o.x = acc[i][0]; o.y = acc[i][1]; o.z = acc[i][2]; o.w = acc[i][3];
        *(float4*)(kvo + (d0 + i) * 64 + e0) = o;
    }
    if (tx == 0) {
#pragma unroll
        for (int i = 0; i < 4; i++) ksp[((size_t)ch * 64 + bh) * 64 + d0 + i] = ks[i];
    }
}

// ---------------- reduce partials (deterministic) ----------------
__global__ void reduce_kernel(const float* __restrict__ kvp,
                              const float* __restrict__ ksp,
                              float* __restrict__ kv, float* __restrict__ ks) {
    int i = blockIdx.x * 256 + threadIdx.x;
    if (i < 64 * 4096) {
        float s = 0.f;
#pragma unroll
        for (int c = 0; c < KCH; c++) s += kvp[(size_t)c * 64 * 4096 + i];
        kv[i] = s;
    }
    if (i < 64 * 64) {
        float s = 0.f;
#pragma unroll
        for (int c = 0; c < KCH; c++) s += ksp[(size_t)c * 64 * 64 + i];
        ks[i] = s;
    }
}

// ---------------- attention core ----------------
__global__ __launch_bounds__(256) void attn_kernel(const float* __restrict__ Qb,
                                                   const float* __restrict__ kv,
                                                   const float* __restrict__ ksum,
                                                   float* __restrict__ Ab) {
    const int bh = blockIdx.x;
    const int b = bh >> 4;
    const int h = bh & 15;
    const int s0 = blockIdx.y * 64;

    __shared__ float kvs[64][64];
    __shared__ float qs[64][64];
    __shared__ float kss[64];

    const int tid = threadIdx.x;

    {
        const float4* src = (const float4*)(kv + (size_t)bh * 4096);
        float4* dst = (float4*)&kvs[0][0];
        for (int i = tid; i < 1024; i += 256) dst[i] = src[i];
    }
    for (int i = tid; i < 64 * 16; i += 256) {
        int r = i >> 4;
        int c4 = (i & 15) * 4;
        *(float4*)&qs[r][c4] =
            *(const float4*)(Qb + (size_t)(b * SEQ + s0 + r) * D_MODEL + h * 64 + c4);
    }
    if (tid < 16) ((float4*)kss)[tid] = ((const float4*)(ksum + bh * 64))[tid];
    __syncthreads();

    const int e = tid & 63;
    const int tsub = tid >> 6;
    for (int t = tsub; t < 64; t += 4) {
        float z = 0.0f, o = 0.0f;
#pragma unroll 16
        for (int d = 0; d < 64; d++) {
            float qd = qs[t][d];
            z = fmaf(qd, kss[d], z);
            o = fmaf(qd, kvs[d][e], o);
        }
        float r = o / (z + EPS);
        unsigned rt;
        asm("cvt.rna.tf32.f32 %0, %1;" : "=r"(rt) : "f"(r));  // round for Wo tf32 GEMM
        Ab[(size_t)(b * SEQ + s0 + t) * D_MODEL + h * 64 + e] = __uint_as_float(rt);
    }
}

// ---------------- launch ----------------
extern "C" void kernel_launch(void* const* d_in, const int* in_sizes, int n_in,
                              void* d_out, int out_size) {
    const float* x  = (const float*)d_in[0];
    const float* Wq = (const float*)d_in[1];
    const float* bq = (const float*)d_in[2];
    const float* Wk = (const float*)d_in[3];
    const float* bk = (const float*)d_in[4];
    const float* Wv = (const float*)d_in[5];
    const float* bv = (const float*)d_in[6];
    const float* Wo = (const float*)d_in[7];
    const float* bo = (const float*)d_in[8];
    float* out = (float*)d_out;

    float *Q, *K, *V, *A, *Xr, *Wr, *kvp, *ksp, *kv, *ks;
    cudaGetSymbolAddress((void**)&Q, g_Q);
    cudaGetSymbolAddress((void**)&K, g_K);
    cudaGetSymbolAddress((void**)&V, g_V);
    cudaGetSymbolAddress((void**)&A, g_A);
    cudaGetSymbolAddress((void**)&Xr, g_Xr);
    cudaGetSymbolAddress((void**)&Wr, g_Wr);
    cudaGetSymbolAddress((void**)&kvp, g_kvp);
    cudaGetSymbolAddress((void**)&ksp, g_ksp);
    cudaGetSymbolAddress((void**)&kv, g_kv);
    cudaGetSymbolAddress((void**)&ks, g_ks);

    cudaFuncSetAttribute(gemm_tf32<0>, cudaFuncAttributeMaxDynamicSharedMemorySize, GEMM_SMEM);
    cudaFuncSetAttribute(gemm_tf32<1>, cudaFuncAttributeMaxDynamicSharedMemorySize, GEMM_SMEM);

    const size_t WN = (size_t)D_MODEL * D_MODEL;  // 1M

    // tf32-round inputs (RNA)
    round_tf32_kernel<<<(NTOK * D_MODEL / 4 + 255) / 256, 256>>>((const float4*)x, (float4*)Xr,
                                                                 NTOK * D_MODEL / 4);
    round_tf32_kernel<<<(WN / 4 + 255) / 256, 256>>>((const float4*)Wq, (float4*)(Wr + 0 * WN), WN / 4);
    round_tf32_kernel<<<(WN / 4 + 255) / 256, 256>>>((const float4*)Wk, (float4*)(Wr + 1 * WN), WN / 4);
    round_tf32_kernel<<<(WN / 4 + 255) / 256, 256>>>((const float4*)Wv, (float4*)(Wr + 2 * WN), WN / 4);
    round_tf32_kernel<<<(WN / 4 + 255) / 256, 256>>>((const float4*)Wo, (float4*)(Wr + 3 * WN), WN / 4);

    dim3 grid(8, 128);
    gemm_tf32<1><<<grid, 256, GEMM_SMEM>>>(Xr, Wr + 0 * WN, bq, Q);
    gemm_tf32<1><<<grid, 256, GEMM_SMEM>>>(Xr, Wr + 1 * WN, bk, K);
    gemm_tf32<0><<<grid, 256, GEMM_SMEM>>>(Xr, Wr + 2 * WN, bv, V);

    kv_kernel<<<dim3(64, KCH), 256>>>(K, V, kvp, ksp);
    reduce_kernel<<<(64 * 4096) / 256, 256>>>(kvp, ksp, kv, ks);
    attn_kernel<<<dim3(64, SEQ / 64), 256>>>(Q, kv, ks, A);

    gemm_tf32<0><<<grid, 256, GEMM_SMEM>>>(A, Wr + 3 * WN, bo, out);
}

// round 4
// speedup vs baseline: 4.3874x; 1.4025x over previous
#include <cuda_runtime.h>
#include <cuda_fp16.h>
#include <math.h>
#include <stdint.h>

#define D_MODEL 1024
#define SEQ     4096
#define BATCH   4
#define NTOK    16384
#define NHEADS  16
#define EPS     1e-6f
#define KCH     8

// ---------------- scratch ----------------
__device__ __half g_Xh[(size_t)NTOK * D_MODEL];
__device__ __half g_Ah[(size_t)NTOK * D_MODEL];
__device__ __half g_Wh[4][(size_t)D_MODEL * D_MODEL];   // transposed [n][k]
__device__ float  g_Q[(size_t)NTOK * D_MODEL];
__device__ float  g_K[(size_t)NTOK * D_MODEL];
__device__ float  g_V[(size_t)NTOK * D_MODEL];
__device__ float  g_kvp[KCH * 64 * 4096];
__device__ float  g_ksp[KCH * 64 * 64];
__device__ float  g_kv[64 * 4096];
__device__ float  g_ks[64 * 64];

// ---------------- fp16 tensor-core GEMM ----------------
// C[M,1024] = A[M,1024](half) @ Bt[1024(n),1024(k)](half, pre-transposed) + bias
// Block 128x128, Ktile 32 halves, 256 thr = 8 warps (2x4), warp tile 64x32.
// Smem rows padded to 56 halves (112B): ldmatrix + scalar loads conflict-free.
#define AST   56                       // halves per smem row (112 bytes)
#define MATB  (128 * AST * 2)          // 14336 bytes per matrix per stage
#define STAGEB (2 * MATB)              // 28672
#define GEMM_SMEM (2 * STAGEB)         // 57344

__device__ __forceinline__ void cpasync16(uint32_t dst, const void* src) {
    asm volatile("cp.async.cg.shared.global [%0], [%1], 16;\n" ::"r"(dst), "l"(src));
}

__device__ __forceinline__ void load_tile(uint32_t sst, const __half* __restrict__ A,
                                          const __half* __restrict__ Bt,
                                          int m0, int n0, int kt, int tid) {
    const __half* Asrc = A + (size_t)m0 * 1024 + kt * 32;
    const __half* Bsrc = Bt + (size_t)n0 * 1024 + kt * 32;
#pragma unroll
    for (int j = 0; j < 2; j++) {
        int c = tid + j * 256;              // 512 chunks of 16B for A
        int row = c >> 2, kc = (c & 3) * 8;
        cpasync16(sst + (uint32_t)(row * 112 + kc * 2), Asrc + (size_t)row * 1024 + kc);
    }
#pragma unroll
    for (int j = 0; j < 2; j++) {
        int c = tid + j * 256;              // 512 chunks for B
        int row = c >> 2, kc = (c & 3) * 8;
        cpasync16(sst + (uint32_t)(MATB + row * 112 + kc * 2),
                  Bsrc + (size_t)row * 1024 + kc);
    }
    asm volatile("cp.async.commit_group;\n" ::: "memory");
}

template <int FMAP>
__global__ void __launch_bounds__(256) gemm_h(const __half* __restrict__ A,
                                              const __half* __restrict__ Bt,
                                              const float* __restrict__ bias,
                                              float* __restrict__ C) {
    extern __shared__ __align__(128) char smem[];
    uint32_t sb;
    asm("{ .reg .u64 t; cvta.to.shared.u64 t, %1; cvt.u32.u64 %0, t; }" : "=r"(sb) : "l"(smem));

    const int tid = threadIdx.x;
    const int lane = tid & 31, w = tid >> 5;
    const int wm = w & 1;                   // m offset *64
    const int wn = w >> 1;                  // n offset *32
    const int m0 = blockIdx.y * 128, n0 = blockIdx.x * 128;

    // A ldmatrix per-lane base: row = wm*64 + (lane&15), khalf = (lane>>4)*8
    const uint32_t aOff = (uint32_t)((wm * 64 + (lane & 15)) * 112 + (lane >> 4) * 16);
    // B scalar per-lane base: row n = wn*32 + lane/4, khalf = (lane&3)*2
    const uint32_t bOff = (uint32_t)(MATB + (wn * 32 + (lane >> 2)) * 112 + (lane & 3) * 4);

    float acc[4][4][4];
#pragma unroll
    for (int i = 0; i < 4; i++)
#pragma unroll
        for (int j = 0; j < 4; j++)
#pragma unroll
            for (int r = 0; r < 4; r++) acc[i][j][r] = 0.0f;

    load_tile(sb, A, Bt, m0, n0, 0, tid);

    for (int kt = 0; kt < 32; kt++) {
        asm volatile("cp.async.wait_group 0;\n" ::: "memory");
        __syncthreads();
        if (kt < 31)
            load_tile(sb + (uint32_t)(((kt + 1) & 1) * STAGEB), A, Bt, m0, n0, kt + 1, tid);
        const uint32_t cs = sb + (uint32_t)((kt & 1) * STAGEB);

#pragma unroll
        for (int ks = 0; ks < 2; ks++) {     // two k16 steps per 32-half tile
            uint32_t a[4][4];
#pragma unroll
            for (int mf = 0; mf < 4; mf++) {
                uint32_t addr = cs + aOff + (uint32_t)(mf * 16 * 112 + ks * 32);
                asm volatile(
                    "ldmatrix.sync.aligned.m8n8.x4.shared.b16 {%0,%1,%2,%3}, [%4];"
                    : "=r"(a[mf][0]), "=r"(a[mf][1]), "=r"(a[mf][2]), "=r"(a[mf][3])
                    : "r"(addr));
            }
            uint32_t bf[4][2];
#pragma unroll
            for (int nf = 0; nf < 4; nf++) {
                uint32_t ba = cs + bOff + (uint32_t)(nf * 8 * 112 + ks * 32);
                asm volatile("ld.shared.b32 %0, [%1];" : "=r"(bf[nf][0]) : "r"(ba));
                asm volatile("ld.shared.b32 %0, [%1];" : "=r"(bf[nf][1]) : "r"(ba + 16));
            }
#pragma unroll
            for (int mf = 0; mf < 4; mf++)
#pragma unroll
                for (int nf = 0; nf < 4; nf++)
                    asm volatile(
                        "mma.sync.aligned.m16n8k16.row.col.f32.f16.f16.f32 "
                        "{%0,%1,%2,%3}, {%4,%5,%6,%7}, {%8,%9}, {%0,%1,%2,%3};"
                        : "+f"(acc[mf][nf][0]), "+f"(acc[mf][nf][1]),
                          "+f"(acc[mf][nf][2]), "+f"(acc[mf][nf][3])
                        : "r"(a[mf][0]), "r"(a[mf][1]), "r"(a[mf][2]), "r"(a[mf][3]),
                          "r"(bf[nf][0]), "r"(bf[nf][1]));
        }
    }

    // epilogue: c0,c1 at (row=lane/4, col=(lane&3)*2), c2,c3 at row+8
    const int gr = lane >> 2, gc2 = (lane & 3) * 2;
#pragma unroll
    for (int mf = 0; mf < 4; mf++) {
        int r0 = m0 + wm * 64 + mf * 16 + gr;
#pragma unroll
        for (int nf = 0; nf < 4; nf++) {
            int col = n0 + wn * 32 + nf * 8 + gc2;
            float2 bb = *(const float2*)(bias + col);
            float v0 = acc[mf][nf][0] + bb.x;
            float v1 = acc[mf][nf][1] + bb.y;
            float v2 = acc[mf][nf][2] + bb.x;
            float v3 = acc[mf][nf][3] + bb.y;
            if (FMAP) {
                v0 = (v0 > 0.0f) ? v0 + 1.0f : expf(v0);
                v1 = (v1 > 0.0f) ? v1 + 1.0f : expf(v1);
                v2 = (v2 > 0.0f) ? v2 + 1.0f : expf(v2);
                v3 = (v3 > 0.0f) ? v3 + 1.0f : expf(v3);
            }
            float2 o0 = {v0, v1}, o1 = {v2, v3};
            *(float2*)(C + (size_t)r0 * 1024 + col) = o0;
            *(float2*)(C + (size_t)(r0 + 8) * 1024 + col) = o1;
        }
    }
}

// ---------------- conversions ----------------
__global__ void to_half_kernel(const float4* __restrict__ in, __half2* __restrict__ out,
                               int n4) {
    int i = blockIdx.x * blockDim.x + threadIdx.x;
    if (i >= n4) return;
    float4 v = in[i];
    out[i * 2]     = __floats2half2_rn(v.x, v.y);
    out[i * 2 + 1] = __floats2half2_rn(v.z, v.w);
}

// Wt[n][k] = half(W[k][n])
__global__ void transpose_half(const float* __restrict__ W, __half* __restrict__ Wt) {
    __shared__ float t[32][33];
    const int bx = blockIdx.x * 32, by = blockIdx.y * 32;
    const int tx = threadIdx.x, ty = threadIdx.y;
#pragma unroll
    for (int j = 0; j < 32; j += 8)
        t[ty + j][tx] = W[(size_t)(by + ty + j) * 1024 + bx + tx];
    __syncthreads();
#pragma unroll
    for (int j = 0; j < 32; j += 8)
        Wt[(size_t)(bx + ty + j) * 1024 + by + tx] = __float2half_rn(t[tx][ty + j]);
}

// ---------------- kv partial ----------------
__global__ __launch_bounds__(256) void kv_kernel(const float* __restrict__ Kb,
                                                 const float* __restrict__ Vb,
                                                 float* __restrict__ kvp,
                                                 float* __restrict__ ksp) {
    const int bh = blockIdx.x;
    const int ch = blockIdx.y;
    const int b = bh >> 4;
    const int h = bh & 15;

    __shared__ float Ks[32][64];
    __shared__ float Vs[32][64];

    const int tid = threadIdx.x;
    const int tx = tid & 15, ty = tid >> 4;
    const int d0 = ty * 4, e0 = tx * 4;

    float acc[4][4];
#pragma unroll
    for (int i = 0; i < 4; i++)
#pragma unroll
        for (int j = 0; j < 4; j++) acc[i][j] = 0.0f;
    float ks[4] = {0.f, 0.f, 0.f, 0.f};

    const float* Kbase = Kb + (size_t)b * SEQ * D_MODEL + h * 64;
    const float* Vbase = Vb + (size_t)b * SEQ * D_MODEL + h * 64;
    const int sBeg = ch * (SEQ / KCH);

    for (int s0 = sBeg; s0 < sBeg + SEQ / KCH; s0 += 32) {
        for (int i = tid; i < 512; i += 256) {
            int r = i >> 4, c4 = (i & 15) * 4;
            *(float4*)&Ks[r][c4] = *(const float4*)(Kbase + (size_t)(s0 + r) * D_MODEL + c4);
            *(float4*)&Vs[r][c4] = *(const float4*)(Vbase + (size_t)(s0 + r) * D_MODEL + c4);
        }
        __syncthreads();
#pragma unroll 8
        for (int s = 0; s < 32; s++) {
            float kd[4], ve[4];
            *(float4*)kd = *(float4*)&Ks[s][d0];
            *(float4*)ve = *(float4*)&Vs[s][e0];
#pragma unroll
            for (int i = 0; i < 4; i++)
#pragma unroll
                for (int j = 0; j < 4; j++) acc[i][j] = fmaf(kd[i], ve[j], acc[i][j]);
            if (tx == 0) {
#pragma unroll
                for (int i = 0; i < 4; i++) ks[i] += kd[i];
            }
        }
        __syncthreads();
    }

    float* kvo = kvp + ((size_t)ch * 64 + bh) * 4096;
#pragma unroll
    for (int i = 0; i < 4; i++) {
        float4 o = {acc[i][0], acc[i][1], acc[i][2], acc[i][3]};
        *(float4*)(kvo + (d0 + i) * 64 + e0) = o;
    }
    if (tx == 0)
#pragma unroll
        for (int i = 0; i < 4; i++) ksp[((size_t)ch * 64 + bh) * 64 + d0 + i] = ks[i];
}

__global__ void reduce_kernel(const float* __restrict__ kvp, const float* __restrict__ ksp,
                              float* __restrict__ kv, float* __restrict__ ks) {
    int i = blockIdx.x * 256 + threadIdx.x;
    if (i < 64 * 4096) {
        float s = 0.f;
#pragma unroll
        for (int c = 0; c < KCH; c++) s += kvp[(size_t)c * 64 * 4096 + i];
        kv[i] = s;
    }
    if (i < 64 * 64) {
        float s = 0.f;
#pragma unroll
        for (int c = 0; c < KCH; c++) s += ksp[(size_t)c * 64 * 64 + i];
        ks[i] = s;
    }
}

// ---------------- attention core (writes half for Wo GEMM) ----------------
__global__ __launch_bounds__(256) void attn_kernel(const float* __restrict__ Qb,
                                                   const float* __restrict__ kv,
                                                   const float* __restrict__ ksum,
                                                   __half* __restrict__ Ah) {
    const int bh = blockIdx.x;
    const int b = bh >> 4;
    const int h = bh & 15;
    const int s0 = blockIdx.y * 64;

    __shared__ float kvs[64][64];
    __shared__ float qs[64][64];
    __shared__ float kss[64];

    const int tid = threadIdx.x;
    {
        const float4* src = (const float4*)(kv + (size_t)bh * 4096);
        float4* dst = (float4*)&kvs[0][0];
        for (int i = tid; i < 1024; i += 256) dst[i] = src[i];
    }
    for (int i = tid; i < 64 * 16; i += 256) {
        int r = i >> 4, c4 = (i & 15) * 4;
        *(float4*)&qs[r][c4] =
            *(const float4*)(Qb + (size_t)(b * SEQ + s0 + r) * D_MODEL + h * 64 + c4);
    }
    if (tid < 16) ((float4*)kss)[tid] = ((const float4*)(ksum + bh * 64))[tid];
    __syncthreads();

    const int e = tid & 63;
    const int tsub = tid >> 6;
    for (int t = tsub; t < 64; t += 4) {
        float z = 0.0f, o = 0.0f;
#pragma unroll 16
        for (int d = 0; d < 64; d++) {
            float qd = qs[t][d];
            z = fmaf(qd, kss[d], z);
            o = fmaf(qd, kvs[d][e], o);
        }
        Ah[(size_t)(b * SEQ + s0 + t) * D_MODEL + h * 64 + e] = __float2half_rn(o / (z + EPS));
    }
}

// ---------------- launch ----------------
extern "C" void kernel_launch(void* const* d_in, const int* in_sizes, int n_in,
                              void* d_out, int out_size) {
    const float* x  = (const float*)d_in[0];
    const float* Wq = (const float*)d_in[1];
    const float* bq = (const float*)d_in[2];
    const float* Wk = (const float*)d_in[3];
    const float* bk = (const float*)d_in[4];
    const float* Wv = (const float*)d_in[5];
    const float* bv = (const float*)d_in[6];
    const float* Wo = (const float*)d_in[7];
    const float* bo = (const float*)d_in[8];
    float* out = (float*)d_out;

    __half *Xh, *Ah, *Wh;
    float *Q, *K, *V, *kvp, *ksp, *kv, *ks;
    cudaGetSymbolAddress((void**)&Xh, g_Xh);
    cudaGetSymbolAddress((void**)&Ah, g_Ah);
    cudaGetSymbolAddress((void**)&Wh, g_Wh);
    cudaGetSymbolAddress((void**)&Q, g_Q);
    cudaGetSymbolAddress((void**)&K, g_K);
    cudaGetSymbolAddress((void**)&V, g_V);
    cudaGetSymbolAddress((void**)&kvp, g_kvp);
    cudaGetSymbolAddress((void**)&ksp, g_ksp);
    cudaGetSymbolAddress((void**)&kv, g_kv);
    cudaGetSymbolAddress((void**)&ks, g_ks);

    cudaFuncSetAttribute(gemm_h<0>, cudaFuncAttributeMaxDynamicSharedMemorySize, GEMM_SMEM);
    cudaFuncSetAttribute(gemm_h<1>, cudaFuncAttributeMaxDynamicSharedMemorySize, GEMM_SMEM);

    const size_t WN = (size_t)D_MODEL * D_MODEL;

    to_half_kernel<<<NTOK * D_MODEL / 4 / 256, 256>>>((const float4*)x, (__half2*)Xh,
                                                      NTOK * D_MODEL / 4);
    dim3 tg(32, 32), tb(32, 8);
    transpose_half<<<tg, tb>>>(Wq, Wh + 0 * WN);
    transpose_half<<<tg, tb>>>(Wk, Wh + 1 * WN);
    transpose_half<<<tg, tb>>>(Wv, Wh + 2 * WN);
    transpose_half<<<tg, tb>>>(Wo, Wh + 3 * WN);

    dim3 grid(8, 128);
    gemm_h<1><<<grid, 256, GEMM_SMEM>>>(Xh, Wh + 0 * WN, bq, Q);
    gemm_h<1><<<grid, 256, GEMM_SMEM>>>(Xh, Wh + 1 * WN, bk, K);
    gemm_h<0><<<grid, 256, GEMM_SMEM>>>(Xh, Wh + 2 * WN, bv, V);

    kv_kernel<<<dim3(64, KCH), 256>>>(K, V, kvp, ksp);
    reduce_kernel<<<(64 * 4096) / 256, 256>>>(kvp, ksp, kv, ks);
    attn_kernel<<<dim3(64, SEQ / 64), 256>>>(Q, kv, ks, Ah);

    gemm_h<0><<<grid, 256, GEMM_SMEM>>>(Ah, Wh + 3 * WN, bo, out);
}